// round 3
// baseline (speedup 1.0000x reference)
#include <cuda_runtime.h>

// ExpandEvecs: out[b,k,n,m] = sum_{j<=k} ev[b,n,j] * ev[b,m,j]
// ev: [B=4, C=1, N=1024, K=16] fp32 ; out: [B, K, N, N] fp32 (256 MB)
// Store-bound. Key lever this round: cut regs (118 -> ~50) by re-loading
// B-values from L1 (evb is 64KB, L1-resident) instead of caching 64 floats
// per thread -> 4 CTAs/SM resident -> 2x outstanding stores per SM.

#define NDIM 1024
#define KDIM 16
#define GRID_BLOCKS 296

__global__ __launch_bounds__(256, 4)
void expand_evecs_kernel(const float* __restrict__ ev,
                         float* __restrict__ out,
                         int n_items) {
    const int tid = threadIdx.x;
    const int m   = tid << 2;            // 4 consecutive m-columns per thread

    // Contiguous chunk of (b,n)-row work items for this block.
    const int per = n_items / GRID_BLOCKS;
    const int rem = n_items % GRID_BLOCKS;
    int start, count;
    if ((int)blockIdx.x < rem) {
        count = per + 1;
        start = blockIdx.x * count;
    } else {
        count = per;
        start = rem * (per + 1) + (blockIdx.x - rem) * per;
    }

    const size_t plane = (size_t)NDIM * NDIM;    // floats per k-plane

    for (int it = start; it < start + count; ++it) {
        const int b = it >> 10;          // NDIM = 1024
        const int n = it & (NDIM - 1);
        const float* evb = ev + (size_t)b * NDIM * KDIM;
        const float4* evb4 = (const float4*)evb;

        // a-row for this n: uniform across the block -> broadcast L1 hits.
        float a[KDIM];
        const float4* arow = (const float4*)(evb + (size_t)n * KDIM);
        #pragma unroll
        for (int q = 0; q < 4; ++q)
            ((float4*)a)[q] = __ldg(arow + q);

        float4 acc = make_float4(0.f, 0.f, 0.f, 0.f);
        float* op = out + ((size_t)b * KDIM * NDIM + n) * NDIM + m;

        #pragma unroll
        for (int kq = 0; kq < 4; ++kq) {
            // 4 B-rows' k-quad values: L1-hit LDG.128s, not register-resident.
            float4 v0 = __ldg(&evb4[(size_t)(m + 0) * 4 + kq]);
            float4 v1 = __ldg(&evb4[(size_t)(m + 1) * 4 + kq]);
            float4 v2 = __ldg(&evb4[(size_t)(m + 2) * 4 + kq]);
            float4 v3 = __ldg(&evb4[(size_t)(m + 3) * 4 + kq]);

            float vb[4][4];
            *(float4*)vb[0] = v0;
            *(float4*)vb[1] = v1;
            *(float4*)vb[2] = v2;
            *(float4*)vb[3] = v3;

            #pragma unroll
            for (int kk = 0; kk < 4; ++kk) {
                const float ak = a[kq * 4 + kk];
                acc.x = fmaf(ak, vb[0][kk], acc.x);
                acc.y = fmaf(ak, vb[1][kk], acc.y);
                acc.z = fmaf(ak, vb[2][kk], acc.z);
                acc.w = fmaf(ak, vb[3][kk], acc.w);
                __stcs((float4*)op, acc);
                op += plane;
            }
        }
    }
}

extern "C" void kernel_launch(void* const* d_in, const int* in_sizes, int n_in,
                              void* d_out, int out_size) {
    const float* ev = (const float*)d_in[0];
    float* out = (float*)d_out;
    const int B = in_sizes[0] / (NDIM * KDIM);   // = 4
    const int n_items = B * NDIM;                // 4096 (b,n) rows
    expand_evecs_kernel<<<GRID_BLOCKS, 256>>>(ev, out, n_items);
}